// round 1
// baseline (speedup 1.0000x reference)
#include <cuda_runtime.h>
#include <math.h>

// Selected patch indices and softmax weights, produced by topk kernel,
// consumed by gather kernel (same stream -> ordered).
__device__ int   g_idx[8];
__device__ float g_w[8];

// ---------------------------------------------------------------------------
// Kernel 1: masked logit + iterative Gumbel top-k (B=1, N=64, K=8).
// One block of 64 threads. Writes masked_logit to out tail, idx/w to globals.
// ---------------------------------------------------------------------------
__global__ void topk_kernel(const float* __restrict__ logit,
                            const float* __restrict__ bg,
                            const float* __restrict__ gumbel,
                            float* __restrict__ out_masked_logit) {
    __shared__ float sp[64];
    __shared__ float red[64];
    __shared__ int   ridx[64];

    const int i = threadIdx.x;  // 0..63
    float ml = logit[i] + logf(fmaxf(1.0f - bg[i], 1e-8f));
    out_masked_logit[i] = ml;
    sp[i] = ml + gumbel[i];
    __syncthreads();

    #pragma unroll 1
    for (int k = 0; k < 8; k++) {
        // argmax (first-max tie-break like jnp.argmax: strict > keeps left/lower idx)
        red[i]  = sp[i];
        ridx[i] = i;
        __syncthreads();
        #pragma unroll
        for (int s = 32; s > 0; s >>= 1) {
            if (i < s) {
                if (red[i + s] > red[i]) { red[i] = red[i + s]; ridx[i] = ridx[i + s]; }
            }
            __syncthreads();
        }
        const float m   = red[0];
        const int   idx = ridx[0];
        __syncthreads();

        // softmax denominator at tau=0.01: sum exp((p_i - m)*100)
        red[i] = expf((sp[i] - m) * 100.0f);
        __syncthreads();
        #pragma unroll
        for (int s = 32; s > 0; s >>= 1) {
            if (i < s) red[i] += red[i + s];
            __syncthreads();
        }
        if (i == 0) {
            g_idx[k] = idx;
            g_w[k]   = 1.0f / red[0];   // exp(0)/sum
        }
        __syncthreads();
        if (i == idx) sp[i] -= 1e9f;    // mask out selected (matches NEG accumulation)
        __syncthreads();
    }
}

// ---------------------------------------------------------------------------
// Kernel 2: gather selected patches (float4 vectorized).
//   img_out[k,c,hp,wp,dp] = w[k] * image[c, hi*64+hp, wi*64+wp, di*64+dp]
//   lab_out[k,0,hp,wp,dp] =        label[   hi*64+hp, wi*64+wp, di*64+dp]
// Image region: 2,097,152 float4; label region: 524,288 float4.
// ---------------------------------------------------------------------------
#define IMG_V4  2097152   // 8*4*64*64*16
#define TOT_V4  2621440   // + 8*64*64*16

__global__ void gather_kernel(const float4* __restrict__ img,
                              const float4* __restrict__ lab,
                              float4* __restrict__ out) {
    const int t = blockIdx.x * blockDim.x + threadIdx.x;
    if (t >= TOT_V4) return;

    if (t < IMG_V4) {
        const int dv = t & 15;
        const int wp = (t >> 4) & 63;
        const int hp = (t >> 10) & 63;
        const int c  = (t >> 16) & 3;
        const int k  = t >> 18;
        const int n  = g_idx[k];
        const int hi = n >> 4, wi = (n >> 2) & 3, di = n & 3;
        // source float4 offset: (c*2^24 + (hi*64+hp)*2^16 + (wi*64+wp)*256 + di*64)/4
        const int src = (c << 22) + (((hi << 6) + hp) << 14)
                      + (((wi << 6) + wp) << 6) + (di << 4) + dv;
        const float w = g_w[k];
        float4 v = __ldg(&img[src]);
        v.x *= w; v.y *= w; v.z *= w; v.w *= w;
        out[t] = v;
    } else {
        const int t2 = t - IMG_V4;
        const int dv = t2 & 15;
        const int wp = (t2 >> 4) & 63;
        const int hp = (t2 >> 10) & 63;
        const int k  = t2 >> 16;
        const int n  = g_idx[k];
        const int hi = n >> 4, wi = (n >> 2) & 3, di = n & 3;
        const int src = (((hi << 6) + hp) << 14)
                      + (((wi << 6) + wp) << 6) + (di << 4) + dv;
        out[t] = __ldg(&lab[src]);   // weight is exactly 1 (one_hot only)
    }
}

// ---------------------------------------------------------------------------
// Launch
// ---------------------------------------------------------------------------
extern "C" void kernel_launch(void* const* d_in, const int* in_sizes, int n_in,
                              void* d_out, int out_size) {
    const float* image  = (const float*)d_in[0];  // [1,4,256,256,256]
    const float* label  = (const float*)d_in[1];  // [1,1,256,256,256]
    const float* logit  = (const float*)d_in[2];  // [1,1,4,4,4]
    const float* bgmask = (const float*)d_in[3];  // [1,1,4,4,4]
    const float* gumbel = (const float*)d_in[4];  // [1,64]
    // d_in[5] = k (always 8; out_size fixes K, reading device-side scalar on
    // host would break graph capture)

    float* out = (float*)d_out;
    // layout: img_out [8,4,64,64,64] @0, lab_out [8,1,64,64,64] @8388608,
    //         masked_logit [64] @10485760
    float* out_ml = out + 10485760;

    topk_kernel<<<1, 64>>>(logit, bgmask, gumbel, out_ml);

    const int threads = 256;
    const int blocks  = (TOT_V4 + threads - 1) / threads;  // 10240
    gather_kernel<<<blocks, threads>>>((const float4*)image,
                                       (const float4*)label,
                                       (float4*)d_out);
}

// round 5
// speedup vs baseline: 1.2230x; 1.2230x over previous
#include <cuda_runtime.h>
#include <math.h>

#define IMG_V4   2097152            // 8*4*64*64*16 float4
#define TOT_V4   2621440            // + 8*1*64*64*16
#define NTHREADS 256
#define NBLOCKS  1280
#define STRIDE   (NBLOCKS * NTHREADS)   // 327680
#define ITER     8                       // TOT_V4 / STRIDE exactly

__global__ __launch_bounds__(NTHREADS, 4)
void fused_kernel(const float4* __restrict__ img,
                  const float4* __restrict__ lab,
                  const float*  __restrict__ logit,
                  const float*  __restrict__ bg,
                  const float*  __restrict__ gumbel,
                  float4* __restrict__ out,
                  float*  __restrict__ out_ml)
{
    __shared__ int   sh_base[8];   // float4 offset of patch origin (c=0)
    __shared__ float sh_w[8];      // softmax weight per selection

    // ---- warp 0: masked logit + Gumbel top-8 over 64 entries ----
    if (threadIdx.x < 32) {
        const int lane = threadIdx.x;
        float ml0 = __ldg(logit + lane)      + logf(fmaxf(1.0f - __ldg(bg + lane),      1e-8f));
        float ml1 = __ldg(logit + lane + 32) + logf(fmaxf(1.0f - __ldg(bg + lane + 32), 1e-8f));
        if (blockIdx.x == 0) { out_ml[lane] = ml0; out_ml[lane + 32] = ml1; }

        const float o0 = ml0 + __ldg(gumbel + lane);
        const float o1 = ml1 + __ldg(gumbel + lane + 32);
        float p0 = o0, p1 = o1;
        int   j0 = 8,  j1 = 8;       // step at which my element got selected
        float m[8]; int sel[8];

        #pragma unroll
        for (int k = 0; k < 8; k++) {
            float v; int idx;
            if (p1 > p0) { v = p1; idx = lane + 32; } else { v = p0; idx = lane; }
            #pragma unroll
            for (int s = 16; s > 0; s >>= 1) {
                float ov = __shfl_xor_sync(0xffffffffu, v,   s);
                int   oi = __shfl_xor_sync(0xffffffffu, idx, s);
                if (ov > v || (ov == v && oi < idx)) { v = ov; idx = oi; }
            }
            m[k] = v; sel[k] = idx;
            if (idx == lane)      { j0 = k; p0 = -1e30f; }
            if (idx == lane + 32) { j1 = k; p1 = -1e30f; }
        }

        // all 8 softmax denominators in parallel (exp arg <= 0 always)
        float acc[8];
        #pragma unroll
        for (int k = 0; k < 8; k++) {
            float a = (k <= j0) ? expf((o0 - m[k]) * 100.0f) : 0.0f;
            if (k <= j1)  a +=    expf((o1 - m[k]) * 100.0f);
            acc[k] = a;
        }
        #pragma unroll
        for (int s = 16; s > 0; s >>= 1) {
            #pragma unroll
            for (int k = 0; k < 8; k++)
                acc[k] += __shfl_xor_sync(0xffffffffu, acc[k], s);
        }

        if (lane == 0) {
            #pragma unroll
            for (int k = 0; k < 8; k++) {
                const int n  = sel[k];
                const int hi = n >> 4, wi = (n >> 2) & 3, di = n & 3;
                sh_base[k] = (hi << 20) | (wi << 12) | (di << 4);
                sh_w[k]    = 1.0f / acc[k];
            }
        }
    }
    __syncthreads();

    // ---- gather: 8 float4 per thread, loads front-batched ----
    const int e = blockIdx.x * NTHREADS + threadIdx.x;

    float4 vals[ITER];
    float  ws[ITER];

    #pragma unroll
    for (int it = 0; it < ITER; it++) {
        const int t = e + it * STRIDE;
        int src, k;
        const float4* p;
        if (t < IMG_V4) {
            k   = t >> 18;
            src = (((t >> 16) & 3) << 22) + sh_base[k]
                + (((t >> 10) & 63) << 14) + (((t >> 4) & 63) << 6) + (t & 15);
            p      = img;
            ws[it] = sh_w[k];
        } else {
            const int t2 = t - IMG_V4;
            k   = t2 >> 16;
            src = sh_base[k]
                + (((t2 >> 10) & 63) << 14) + (((t2 >> 4) & 63) << 6) + (t2 & 15);
            p      = lab;
            ws[it] = 1.0f;
        }
        vals[it] = __ldg(&p[src]);
    }

    #pragma unroll
    for (int it = 0; it < ITER; it++) {
        float4 v = vals[it];
        const float w = ws[it];
        v.x *= w; v.y *= w; v.z *= w; v.w *= w;
        out[e + it * STRIDE] = v;
    }
}

extern "C" void kernel_launch(void* const* d_in, const int* in_sizes, int n_in,
                              void* d_out, int out_size) {
    const float* image  = (const float*)d_in[0];  // [1,4,256,256,256]
    const float* label  = (const float*)d_in[1];  // [1,1,256,256,256]
    const float* logit  = (const float*)d_in[2];  // [1,1,4,4,4]
    const float* bgmask = (const float*)d_in[3];  // [1,1,4,4,4]
    const float* gumbel = (const float*)d_in[4];  // [1,64]
    // d_in[5] = k (fixed at 8 by out_size)

    float* out    = (float*)d_out;
    float* out_ml = out + 10485760;   // img[8,4,64^3] + lab[8,1,64^3]

    fused_kernel<<<NBLOCKS, NTHREADS>>>((const float4*)image,
                                        (const float4*)label,
                                        logit, bgmask, gumbel,
                                        (float4*)d_out, out_ml);
}